// round 2
// baseline (speedup 1.0000x reference)
#include <cuda_runtime.h>

#define NN 100000
#define EE 3200000

// ---- scratch (device globals; no allocations anywhere) ----
static __device__ float2 g_deg[NN];                  // (out_deg, in_deg)
static __device__ float  g_outn[NN];                 // out_deg^-1/2
static __device__ float  g_inn[NN];                  // in_deg^-1/2
static __device__ float2 g_ac[NN];                   // (a = outn*weight, outn)  source values
static __device__ float2 g_S[NN];                    // accumulated (Sa, Sc), incl. self-loop
static __device__ float  g_uvw[192];                 // u[64] | v[64] | w2[64]
static __device__ float  g_c0[1];                    // bc2 . W_pred + b_pred
static __device__ __align__(16) float g_p[NN * 64];  // projected feats (middle SpMM source)
static __device__ __align__(16) float g_agg[NN * 64];// middle SpMM accumulator
static __device__ float2 g_q[NN];                    // (q, Sq) for final scalar SpMM

__device__ __forceinline__ float leaky(float x) { return (x > 0.0f) ? x : 0.01f * x; }

__device__ __forceinline__ void red2(float2* p, float2 v) {
    asm volatile("red.global.add.v2.f32 [%0], {%1,%2};"
                 :: "l"(p), "f"(v.x), "f"(v.y) : "memory");
}
__device__ __forceinline__ void red4(float* p, float4 v) {
    asm volatile("red.global.add.v4.f32 [%0], {%1,%2,%3,%4};"
                 :: "l"(p), "f"(v.x), "f"(v.y), "f"(v.z), "f"(v.w) : "memory");
}

// ---------------- degree / norm ----------------
__global__ void k_deg_init() {
    int i = blockIdx.x * blockDim.x + threadIdx.x;
    if (i < NN) g_deg[i] = make_float2(1.0f, 1.0f);   // self-loop contributes 1 to each
}

__global__ void k_deg(const int* __restrict__ src, const int* __restrict__ dst) {
    int e = blockIdx.x * blockDim.x + threadIdx.x;
    if (e < EE) {
        atomicAdd(&g_deg[src[e]].x, 1.0f);
        atomicAdd(&g_deg[dst[e]].y, 1.0f);
    }
}

__global__ void k_norm(const float* __restrict__ weight) {
    int i = blockIdx.x * blockDim.x + threadIdx.x;
    if (i < NN) {
        float2 dg = g_deg[i];
        float on = rsqrtf(dg.x);                      // deg >= 1, clip is a no-op
        float in = rsqrtf(dg.y);
        g_outn[i] = on;
        g_inn[i]  = in;
        float2 ac = make_float2(on * weight[i], on);
        g_ac[i] = ac;
        g_S[i]  = ac;                                 // self-loop init of (Sa, Sc)
    }
}

// ---------------- tiny precompute: u=W_in@Wc0, v=b_in@Wc0, w2=Wc2@W_pred, c0 ----------------
__global__ void k_uv(const float* __restrict__ W_in, const float* __restrict__ b_in,
                     const float* __restrict__ Wc, const float* __restrict__ bc,
                     const float* __restrict__ W_pred, const float* __restrict__ b_pred) {
    __shared__ float sred[64];
    int t = threadIdx.x;  // 64 threads
    float u = 0.0f, v = 0.0f, w2 = 0.0f;
    #pragma unroll
    for (int d = 0; d < 64; d++) {
        float w0 = Wc[d * 64 + t];                    // Wc0[d][t]
        u += W_in[d] * w0;
        v += b_in[d] * w0;
        w2 += Wc[2 * 4096 + t * 64 + d] * W_pred[d];  // (Wc2 @ W_pred)[t]
    }
    g_uvw[t]       = u;
    g_uvw[64 + t]  = v;
    g_uvw[128 + t] = w2;
    sred[t] = bc[128 + t] * W_pred[t];                // bc2[t]*W_pred[t]
    __syncthreads();
    if (t == 0) {
        float s = 0.0f;
        #pragma unroll
        for (int k = 0; k < 64; k++) s += sred[k];
        g_c0[0] = s + b_pred[0];
    }
}

// ---------------- layer-1 scalar SpMM: (Sa,Sc)[dst] += (a,outn)[src] ----------------
__global__ void k_Sac(const int* __restrict__ src, const int* __restrict__ dst) {
    int e = blockIdx.x * blockDim.x + threadIdx.x;
    if (e >= EE) return;
    int s = __ldg(src + e);
    int d = __ldg(dst + e);
    float2 ac = __ldg(&g_ac[s]);
    red2(&g_S[d], ac);
}

// ---------------- dense 1 (fused rank-2 expand + conv0 epilogue + conv1 projection) ----
// agg1[n,j] = Sa[n]*u[j] + Sc[n]*v[j]
// h = leaky(agg1*inn + bc0) * outn ;  p1 = h @ Wc1 ;  agg = p1 (self-loop init)
__global__ __launch_bounds__(256) void k_dense1(const float* __restrict__ W,
                                                const float* __restrict__ bcur) {
    __shared__ float Ws[64 * 64];
    __shared__ float Hs[8][64];
    int tid = threadIdx.x;
    #pragma unroll
    for (int i = 0; i < 16; i++) Ws[i * 256 + tid] = W[i * 256 + tid];
    __syncthreads();

    int warp = tid >> 5, lane = tid & 31;
    int n = blockIdx.x * 8 + warp;
    if (n >= NN) return;

    float2 S  = g_S[n];
    float2 u2 = ((const float2*)g_uvw)[lane];
    float2 v2 = ((const float2*)(g_uvw + 64))[lane];
    float2 bv = ((const float2*)bcur)[lane];
    float innv = g_inn[n], outv = g_outn[n];

    float hx = leaky((S.x * u2.x + S.y * v2.x) * innv + bv.x) * outv;
    float hy = leaky((S.x * u2.y + S.y * v2.y) * innv + bv.y) * outv;
    Hs[warp][2 * lane]     = hx;
    Hs[warp][2 * lane + 1] = hy;
    __syncwarp();

    float acc0 = 0.0f, acc1 = 0.0f;
    const float4* h4 = (const float4*)Hs[warp];
    #pragma unroll
    for (int d4 = 0; d4 < 16; d4++) {
        float4 hv = h4[d4];
        int base = d4 * 256;
        acc0 += hv.x * Ws[base + lane];        acc1 += hv.x * Ws[base + lane + 32];
        acc0 += hv.y * Ws[base + 64 + lane];   acc1 += hv.y * Ws[base + 64 + lane + 32];
        acc0 += hv.z * Ws[base + 128 + lane];  acc1 += hv.z * Ws[base + 128 + lane + 32];
        acc0 += hv.w * Ws[base + 192 + lane];  acc1 += hv.w * Ws[base + 192 + lane + 32];
    }
    g_p[n * 64 + lane]        = acc0;
    g_p[n * 64 + lane + 32]   = acc1;
    g_agg[n * 64 + lane]      = acc0;   // self-loop contribution for middle SpMM
    g_agg[n * 64 + lane + 32] = acc1;
}

// ---------------- middle SpMM (the only full 64-dim one): agg[dst] += p[src] --------
__global__ void k_edges(const int* __restrict__ src, const int* __restrict__ dst) {
    unsigned gid = blockIdx.x * blockDim.x + threadIdx.x;
    unsigned e = gid >> 4;
    if (e >= EE) return;
    int q = gid & 15;
    int s = __ldg(src + e);
    int d = __ldg(dst + e);
    float4 val = __ldg((const float4*)g_p + (s << 4) + q);
    red4(&g_agg[(d << 6) + (q << 2)], val);
}

// ---------------- dense 2 + scalar projection: q[n] = h2[n,:] . w2 ------------------
// h2 = leaky(agg*inn + bc1) * outn ;  g_q[n] = (q, q)   (self-loop init of Sq)
__global__ void k_dense2q(const float* __restrict__ bcur) {
    int tid = blockIdx.x * blockDim.x + threadIdx.x;
    int n = tid >> 5, lane = tid & 31;
    if (n >= NN) return;
    float2 av = ((const float2*)(g_agg + n * 64))[lane];
    float2 bv = ((const float2*)bcur)[lane];
    float2 wv = ((const float2*)(g_uvw + 128))[lane];
    float innv = g_inn[n], outv = g_outn[n];
    float h0 = leaky(av.x * innv + bv.x) * outv;
    float h1 = leaky(av.y * innv + bv.y) * outv;
    float s = h0 * wv.x + h1 * wv.y;
    #pragma unroll
    for (int o = 16; o > 0; o >>= 1) s += __shfl_xor_sync(0xffffffffu, s, o);
    if (lane == 0) g_q[n] = make_float2(s, s);
}

// ---------------- layer-3 scalar SpMM: Sq[dst] += q[src] ----------------------------
__global__ void k_qedges(const int* __restrict__ src, const int* __restrict__ dst) {
    int e = blockIdx.x * blockDim.x + threadIdx.x;
    if (e >= EE) return;
    int s = __ldg(src + e);
    int d = __ldg(dst + e);
    float qv = __ldg(&g_q[s].x);
    atomicAdd(&g_q[d].y, qv);
}

// ---------------- final: out[n] = inn[n]*Sq[n] + c0 ---------------------------------
__global__ void k_final(float* __restrict__ out) {
    int i = blockIdx.x * blockDim.x + threadIdx.x;
    if (i < NN) out[i] = g_inn[i] * g_q[i].y + g_c0[0];
}

extern "C" void kernel_launch(void* const* d_in, const int* in_sizes, int n_in,
                              void* d_out, int out_size) {
    const float* weight = (const float*)d_in[0];
    const int*   src    = (const int*)d_in[1];
    const int*   dst    = (const int*)d_in[2];
    const float* W_in   = (const float*)d_in[3];
    const float* b_in   = (const float*)d_in[4];
    const float* Wc     = (const float*)d_in[5];   // [3,64,64]
    const float* bc     = (const float*)d_in[6];   // [3,64]
    const float* W_pred = (const float*)d_in[7];   // [64,1]
    const float* b_pred = (const float*)d_in[8];
    float* out = (float*)d_out;

    (void)in_sizes; (void)n_in; (void)out_size;

    const int EB = (EE + 255) / 256;
    const int NB = (NN + 255) / 256;

    k_deg_init<<<NB, 256>>>();
    k_deg<<<EB, 256>>>(src, dst);
    k_norm<<<NB, 256>>>(weight);
    k_uv<<<1, 64>>>(W_in, b_in, Wc, bc, W_pred, b_pred);

    // conv 0: scalar rank-2 SpMM
    k_Sac<<<EB, 256>>>(src, dst);

    // conv0 epilogue + conv1 projection (fused)
    k_dense1<<<(NN + 7) / 8, 256>>>(Wc + 4096, bc);       // Wc[1], bc[0]

    // conv 1: the only full 64-dim SpMM
    k_edges<<<(EE * 16) / 256, 256>>>(src, dst);

    // conv1 epilogue + conv2 projection collapsed to scalar q = h2 . (Wc2@W_pred)
    k_dense2q<<<(NN * 32 + 255) / 256, 256>>>(bc + 64);   // bc[1]

    // conv 2: scalar SpMM
    k_qedges<<<EB, 256>>>(src, dst);

    k_final<<<NB, 256>>>(out);
}

// round 5
// speedup vs baseline: 1.3779x; 1.3779x over previous
#include <cuda_runtime.h>

#define NN 100000
#define EE 3200000
#define SCAN_B 512
#define NBLK_SCAN ((NN + SCAN_B - 1) / SCAN_B)   // 196

// ---- scratch (device globals; no allocations anywhere) ----
static __device__ int    g_cntO[NN];                 // out-edge count (excl self)
static __device__ int    g_cntI[NN];                 // in-edge count  (excl self) == CSR row len
static __device__ int    g_cursor[NN];               // scatter cursors
static __device__ int    g_rowstart[NN];             // CSR row offsets
static __device__ int    g_bsum[NBLK_SCAN];          // scan block sums
static __device__ int    g_eidx[EE];                 // CSR: src ids grouped by dst
static __device__ float  g_outn[NN];                 // out_deg^-1/2
static __device__ float  g_inn[NN];                  // in_deg^-1/2
static __device__ float2 g_ac[NN];                   // (a = outn*weight, outn)
static __device__ float  g_uvw[192];                 // u[64] | v[64] | w2[64]
static __device__ float  g_c0[1];                    // bc2 . W_pred + b_pred
static __device__ __align__(16) float g_p[NN * 64];  // projected feats (middle SpMM source)
static __device__ float  g_q[NN];                    // scalar q per node

__device__ __forceinline__ float leaky(float x) { return (x > 0.0f) ? x : 0.01f * x; }

// ---------------- init / degree ----------------
__global__ void k_init() {
    int i = blockIdx.x * blockDim.x + threadIdx.x;
    if (i < NN) { g_cntO[i] = 0; g_cntI[i] = 0; g_cursor[i] = 0; }
}

__global__ void k_deg(const int* __restrict__ src, const int* __restrict__ dst) {
    int e = blockIdx.x * blockDim.x + threadIdx.x;
    if (e < EE) {
        atomicAdd(&g_cntO[src[e]], 1);
        atomicAdd(&g_cntI[dst[e]], 1);
    }
}

__global__ void k_norm(const float* __restrict__ weight) {
    int i = blockIdx.x * blockDim.x + threadIdx.x;
    if (i < NN) {
        float on = rsqrtf((float)(g_cntO[i] + 1));   // +1 self-loop; deg>=1 so clip no-op
        float in = rsqrtf((float)(g_cntI[i] + 1));
        g_outn[i] = on;
        g_inn[i]  = in;
        g_ac[i]   = make_float2(on * weight[i], on);
    }
}

// ---------------- prefix scan of g_cntI -> g_rowstart (exclusive) ----------------
__global__ void k_scan1() {
    __shared__ int sh[SCAN_B];
    int tid = threadIdx.x;
    int i = blockIdx.x * SCAN_B + tid;
    int v = (i < NN) ? g_cntI[i] : 0;
    sh[tid] = v;
    __syncthreads();
    for (int off = 1; off < SCAN_B; off <<= 1) {
        int t = (tid >= off) ? sh[tid - off] : 0;
        __syncthreads();
        sh[tid] += t;
        __syncthreads();
    }
    if (i < NN) g_rowstart[i] = sh[tid] - v;         // exclusive within block
    if (tid == SCAN_B - 1) g_bsum[blockIdx.x] = sh[tid];
}

__global__ void k_scan2() {
    if (threadIdx.x == 0) {
        int run = 0;
        for (int b = 0; b < NBLK_SCAN; b++) { int t = g_bsum[b]; g_bsum[b] = run; run += t; }
    }
}

__global__ void k_scan3() {
    int i = blockIdx.x * SCAN_B + threadIdx.x;
    if (i < NN) g_rowstart[i] += g_bsum[blockIdx.x];
}

// ---------------- scatter: build CSR ----------------
__global__ void k_scatter(const int* __restrict__ src, const int* __restrict__ dst) {
    int e = blockIdx.x * blockDim.x + threadIdx.x;
    if (e < EE) {
        int d = dst[e];
        int pos = atomicAdd(&g_cursor[d], 1);
        g_eidx[g_rowstart[d] + pos] = src[e];
    }
}

// ---------------- tiny precompute, warp-per-output ----------------
// warps 0..63: u[w], v[w]; warps 64..127: w2[w-64]; warp 128: c0
__global__ void k_uv(const float* __restrict__ W_in, const float* __restrict__ b_in,
                     const float* __restrict__ Wc, const float* __restrict__ bc,
                     const float* __restrict__ W_pred, const float* __restrict__ b_pred) {
    int gw = (blockIdx.x * blockDim.x + threadIdx.x) >> 5;
    int lane = threadIdx.x & 31;
    if (gw < 64) {
        int j = gw;
        float u = 0.0f, v = 0.0f;
        #pragma unroll
        for (int c = 0; c < 2; c++) {
            int d = c * 32 + lane;
            float w0 = Wc[d * 64 + j];
            u += W_in[d] * w0;
            v += b_in[d] * w0;
        }
        #pragma unroll
        for (int o = 16; o > 0; o >>= 1) {
            u += __shfl_xor_sync(0xffffffffu, u, o);
            v += __shfl_xor_sync(0xffffffffu, v, o);
        }
        if (lane == 0) { g_uvw[j] = u; g_uvw[64 + j] = v; }
    } else if (gw < 128) {
        int t = gw - 64;
        float w2 = 0.0f;
        #pragma unroll
        for (int c = 0; c < 2; c++) {
            int d = c * 32 + lane;
            w2 += Wc[2 * 4096 + t * 64 + d] * W_pred[d];
        }
        #pragma unroll
        for (int o = 16; o > 0; o >>= 1) w2 += __shfl_xor_sync(0xffffffffu, w2, o);
        if (lane == 0) g_uvw[128 + t] = w2;
    } else if (gw == 128) {
        float s = 0.0f;
        #pragma unroll
        for (int c = 0; c < 2; c++) {
            int d = c * 32 + lane;
            s += bc[128 + d] * W_pred[d];
        }
        #pragma unroll
        for (int o = 16; o > 0; o >>= 1) s += __shfl_xor_sync(0xffffffffu, s, o);
        if (lane == 0) g_c0[0] = s + b_pred[0];
    }
}

// ---------------- dense 1 (fused): conv0 scalar SpMM + rank-2 expand
//                  + conv0 epilogue + conv1 projection -----------------------------
// Warp per node: (Sa,Sc) = self + sum over in-edges of (a,outn)[src];
// agg1[j] = Sa*u[j] + Sc*v[j]; h = leaky(agg1*inn + bc0)*outn; p1 = h @ Wc1.
__global__ __launch_bounds__(256) void k_dense1(const float* __restrict__ W,
                                                const float* __restrict__ bcur) {
    __shared__ float Ws[64 * 64];
    __shared__ float Hs[8][64];
    int tid = threadIdx.x;
    #pragma unroll
    for (int i = 0; i < 16; i++) Ws[i * 256 + tid] = W[i * 256 + tid];
    __syncthreads();

    int warp = tid >> 5, lane = tid & 31;
    int n = blockIdx.x * 8 + warp;
    if (n >= NN) return;

    // --- conv0 scalar SpMM (CSR row sum, lane-per-edge) ---
    int start = g_rowstart[n], len = g_cntI[n];
    float sa = 0.0f, sc = 0.0f;
    for (int base = 0; base < len; base += 32) {
        if (base + lane < len) {
            int s = __ldg(&g_eidx[start + base + lane]);
            float2 ac = __ldg(&g_ac[s]);
            sa += ac.x; sc += ac.y;
        }
    }
    #pragma unroll
    for (int o = 16; o > 0; o >>= 1) {
        sa += __shfl_xor_sync(0xffffffffu, sa, o);
        sc += __shfl_xor_sync(0xffffffffu, sc, o);
    }
    float2 self = __ldg(&g_ac[n]);
    float Sa = self.x + sa;
    float Sc = self.y + sc;

    // --- rank-2 expand + epilogue ---
    float2 u2 = ((const float2*)g_uvw)[lane];
    float2 v2 = ((const float2*)(g_uvw + 64))[lane];
    float2 bv = ((const float2*)bcur)[lane];
    float innv = g_inn[n], outv = g_outn[n];

    float hx = leaky((Sa * u2.x + Sc * v2.x) * innv + bv.x) * outv;
    float hy = leaky((Sa * u2.y + Sc * v2.y) * innv + bv.y) * outv;
    Hs[warp][2 * lane]     = hx;
    Hs[warp][2 * lane + 1] = hy;
    __syncwarp();

    // --- conv1 projection: p1 = h @ Wc1 ---
    float acc0 = 0.0f, acc1 = 0.0f;
    const float4* h4 = (const float4*)Hs[warp];
    #pragma unroll
    for (int d4 = 0; d4 < 16; d4++) {
        float4 hv = h4[d4];
        int base = d4 * 256;
        acc0 += hv.x * Ws[base + lane];        acc1 += hv.x * Ws[base + lane + 32];
        acc0 += hv.y * Ws[base + 64 + lane];   acc1 += hv.y * Ws[base + 64 + lane + 32];
        acc0 += hv.z * Ws[base + 128 + lane];  acc1 += hv.z * Ws[base + 128 + lane + 32];
        acc0 += hv.w * Ws[base + 192 + lane];  acc1 += hv.w * Ws[base + 192 + lane + 32];
    }
    g_p[n * 64 + lane]      = acc0;
    g_p[n * 64 + lane + 32] = acc1;
}

// ---------------- middle SpMM, CSR row-wise (warp-per-row, lane owns 2 dims) ------
// fused conv-2 epilogue + scalar projection: g_q[n] = h2[n,:] . w2
__global__ __launch_bounds__(256) void k_edges_csr(const float* __restrict__ bcur) {
    int gw = (blockIdx.x * blockDim.x + threadIdx.x) >> 5;
    int lane = threadIdx.x & 31;
    if (gw >= NN) return;
    int n = gw;
    const float2* p2 = (const float2*)g_p;

    float2 acc = __ldg(&p2[n * 32 + lane]);          // self-loop contribution
    int start = g_rowstart[n], len = g_cntI[n];
    const int* ep = g_eidx + start;

    int base = 0;
    for (; base + 32 <= len; base += 32) {
        int s_l = __ldg(ep + base + lane);
        #pragma unroll 8
        for (int k = 0; k < 32; k++) {
            int s = __shfl_sync(0xffffffffu, s_l, k);
            float2 v = __ldg(&p2[s * 32 + lane]);
            acc.x += v.x; acc.y += v.y;
        }
    }
    int rem = len - base;
    if (rem > 0) {
        int s_l = (lane < rem) ? __ldg(ep + base + lane) : 0;
        for (int k = 0; k < rem; k++) {
            int s = __shfl_sync(0xffffffffu, s_l, k);
            float2 v = __ldg(&p2[s * 32 + lane]);
            acc.x += v.x; acc.y += v.y;
        }
    }

    // epilogue: h2 = leaky(acc*inn + bc1)*outn; q = h2 . w2
    float innv = g_inn[n], outv = g_outn[n];
    float2 bv = ((const float2*)bcur)[lane];
    float2 wv = ((const float2*)(g_uvw + 128))[lane];
    float h0 = leaky(acc.x * innv + bv.x) * outv;
    float h1 = leaky(acc.y * innv + bv.y) * outv;
    float s = h0 * wv.x + h1 * wv.y;
    #pragma unroll
    for (int o = 16; o > 0; o >>= 1) s += __shfl_xor_sync(0xffffffffu, s, o);
    if (lane == 0) g_q[n] = s;
}

// ---------------- conv-2 scalar SpMM (CSR) + final output -------------------------
__global__ __launch_bounds__(256) void k_q_csr(float* __restrict__ out) {
    int gw = (blockIdx.x * blockDim.x + threadIdx.x) >> 5;
    int lane = threadIdx.x & 31;
    if (gw >= NN) return;
    int start = g_rowstart[gw], len = g_cntI[gw];
    float acc = 0.0f;
    for (int base = 0; base < len; base += 32) {
        if (base + lane < len) {
            int s = __ldg(&g_eidx[start + base + lane]);
            acc += __ldg(&g_q[s]);
        }
    }
    #pragma unroll
    for (int o = 16; o > 0; o >>= 1) acc += __shfl_xor_sync(0xffffffffu, acc, o);
    if (lane == 0) out[gw] = g_inn[gw] * (__ldg(&g_q[gw]) + acc) + g_c0[0];
}

extern "C" void kernel_launch(void* const* d_in, const int* in_sizes, int n_in,
                              void* d_out, int out_size) {
    const float* weight = (const float*)d_in[0];
    const int*   src    = (const int*)d_in[1];
    const int*   dst    = (const int*)d_in[2];
    const float* W_in   = (const float*)d_in[3];
    const float* b_in   = (const float*)d_in[4];
    const float* Wc     = (const float*)d_in[5];   // [3,64,64]
    const float* bc     = (const float*)d_in[6];   // [3,64]
    const float* W_pred = (const float*)d_in[7];   // [64,1]
    const float* b_pred = (const float*)d_in[8];
    float* out = (float*)d_out;

    (void)in_sizes; (void)n_in; (void)out_size;

    const int EB = (EE + 255) / 256;
    const int NB = (NN + 255) / 256;
    const int WB = (NN * 32 + 255) / 256;          // warp-per-row grids

    k_init<<<NB, 256>>>();
    k_deg<<<EB, 256>>>(src, dst);
    k_norm<<<NB, 256>>>(weight);
    k_scan1<<<NBLK_SCAN, SCAN_B>>>();
    k_scan2<<<1, 32>>>();
    k_scan3<<<NBLK_SCAN, SCAN_B>>>();
    k_scatter<<<EB, 256>>>(src, dst);
    k_uv<<<17, 256>>>(W_in, b_in, Wc, bc, W_pred, b_pred);

    k_dense1<<<(NN + 7) / 8, 256>>>(Wc + 4096, bc);  // conv0 SpMM + epilogue + conv1 proj
    k_edges_csr<<<WB, 256>>>(bc + 64);               // conv1 SpMM + conv2 epilogue/proj
    k_q_csr<<<WB, 256>>>(out);                       // conv2 scalar SpMM + predictor
}

// round 6
// speedup vs baseline: 1.4397x; 1.0448x over previous
#include <cuda_runtime.h>
#include <cuda_fp16.h>

#define NN 100000
#define EE 3200000
#define SCAN_B 512
#define NBLK_SCAN ((NN + SCAN_B - 1) / SCAN_B)   // 196

// ---- scratch (device globals; no allocations anywhere) ----
static __device__ int     g_cntO[NN];                 // out-edge count (excl self)
static __device__ int     g_cntI[NN];                 // in-edge count  (excl self) == CSR row len
static __device__ int     g_cursor[NN];               // scatter cursors (absolute)
static __device__ int     g_rowstart[NN];             // CSR row offsets
static __device__ int     g_bsum[NBLK_SCAN];          // scan block sums
static __device__ int     g_eidx[EE];                 // CSR: src ids grouped by dst
static __device__ float   g_outn[NN];                 // out_deg^-1/2
static __device__ float   g_inn[NN];                  // in_deg^-1/2
static __device__ float2  g_ac[NN];                   // (a = outn*weight, outn)
static __device__ float   g_uvw[192];                 // u[64] | v[64] | w2[64]
static __device__ float   g_c0[1];                    // bc2 . W_pred + b_pred
static __device__ __align__(16) __half2 g_ph[NN * 32];// fp16 projected feats (middle SpMM src)
static __device__ float   g_q[NN];                    // scalar q per node

__device__ __forceinline__ float leaky(float x) { return (x > 0.0f) ? x : 0.01f * x; }

// ---------------- init / degree ----------------
__global__ void k_init() {
    int i = blockIdx.x * blockDim.x + threadIdx.x;
    if (i < NN) { g_cntO[i] = 0; g_cntI[i] = 0; }
}

__global__ void k_deg(const int* __restrict__ src, const int* __restrict__ dst) {
    int e = blockIdx.x * blockDim.x + threadIdx.x;
    if (e < EE) {
        atomicAdd(&g_cntO[src[e]], 1);
        atomicAdd(&g_cntI[dst[e]], 1);
    }
}

// ---------------- scan1 (+ fused norm computation) ----------------
__global__ void k_scan1(const float* __restrict__ weight) {
    __shared__ int sh[SCAN_B];
    int tid = threadIdx.x;
    int i = blockIdx.x * SCAN_B + tid;
    int v = (i < NN) ? g_cntI[i] : 0;
    sh[tid] = v;

    // fused per-node norm computation (independent of the scan)
    if (i < NN) {
        float on = rsqrtf((float)(g_cntO[i] + 1));   // +1 self-loop; deg>=1, clip no-op
        float in = rsqrtf((float)(v + 1));
        g_outn[i] = on;
        g_inn[i]  = in;
        g_ac[i]   = make_float2(on * weight[i], on);
    }

    __syncthreads();
    for (int off = 1; off < SCAN_B; off <<= 1) {
        int t = (tid >= off) ? sh[tid - off] : 0;
        __syncthreads();
        sh[tid] += t;
        __syncthreads();
    }
    if (i < NN) g_rowstart[i] = sh[tid] - v;         // exclusive within block
    if (tid == SCAN_B - 1) g_bsum[blockIdx.x] = sh[tid];
}

__global__ void k_scan2() {
    __shared__ int sh[256];
    int t = threadIdx.x;
    int v = (t < NBLK_SCAN) ? g_bsum[t] : 0;
    sh[t] = v;
    __syncthreads();
    for (int off = 1; off < 256; off <<= 1) {
        int x = (t >= off) ? sh[t - off] : 0;
        __syncthreads();
        sh[t] += x;
        __syncthreads();
    }
    if (t < NBLK_SCAN) g_bsum[t] = sh[t] - v;        // exclusive block offsets
}

__global__ void k_scan3() {
    int i = blockIdx.x * SCAN_B + threadIdx.x;
    if (i < NN) {
        int rs = g_rowstart[i] + g_bsum[blockIdx.x];
        g_rowstart[i] = rs;
        g_cursor[i]   = rs;                          // absolute cursor for scatter
    }
}

// ---------------- scatter: build CSR ----------------
__global__ void k_scatter(const int* __restrict__ src, const int* __restrict__ dst) {
    int e = blockIdx.x * blockDim.x + threadIdx.x;
    if (e < EE) {
        int pos = atomicAdd(&g_cursor[dst[e]], 1);   // absolute position
        g_eidx[pos] = src[e];
    }
}

// ---------------- tiny precompute, warp-per-output ----------------
__global__ void k_uv(const float* __restrict__ W_in, const float* __restrict__ b_in,
                     const float* __restrict__ Wc, const float* __restrict__ bc,
                     const float* __restrict__ W_pred, const float* __restrict__ b_pred) {
    int gw = (blockIdx.x * blockDim.x + threadIdx.x) >> 5;
    int lane = threadIdx.x & 31;
    if (gw < 64) {
        int j = gw;
        float u = 0.0f, v = 0.0f;
        #pragma unroll
        for (int c = 0; c < 2; c++) {
            int d = c * 32 + lane;
            float w0 = Wc[d * 64 + j];
            u += W_in[d] * w0;
            v += b_in[d] * w0;
        }
        #pragma unroll
        for (int o = 16; o > 0; o >>= 1) {
            u += __shfl_xor_sync(0xffffffffu, u, o);
            v += __shfl_xor_sync(0xffffffffu, v, o);
        }
        if (lane == 0) { g_uvw[j] = u; g_uvw[64 + j] = v; }
    } else if (gw < 128) {
        int t = gw - 64;
        float w2 = 0.0f;
        #pragma unroll
        for (int c = 0; c < 2; c++) {
            int d = c * 32 + lane;
            w2 += Wc[2 * 4096 + t * 64 + d] * W_pred[d];
        }
        #pragma unroll
        for (int o = 16; o > 0; o >>= 1) w2 += __shfl_xor_sync(0xffffffffu, w2, o);
        if (lane == 0) g_uvw[128 + t] = w2;
    } else if (gw == 128) {
        float s = 0.0f;
        #pragma unroll
        for (int c = 0; c < 2; c++) {
            int d = c * 32 + lane;
            s += bc[128 + d] * W_pred[d];
        }
        #pragma unroll
        for (int o = 16; o > 0; o >>= 1) s += __shfl_xor_sync(0xffffffffu, s, o);
        if (lane == 0) g_c0[0] = s + b_pred[0];
    }
}

// ---------------- dense 1 (fused): conv0 scalar SpMM + rank-2 expand
//                  + conv0 epilogue + conv1 projection (fp16 output) ---------------
// Lane produces adjacent output dims (2*lane, 2*lane+1) -> one __half2 store.
__global__ __launch_bounds__(256) void k_dense1(const float* __restrict__ W,
                                                const float* __restrict__ bcur) {
    __shared__ float Ws[64 * 64];
    __shared__ float Hs[8][64];
    int tid = threadIdx.x;
    #pragma unroll
    for (int i = 0; i < 16; i++) Ws[i * 256 + tid] = W[i * 256 + tid];
    __syncthreads();

    int warp = tid >> 5, lane = tid & 31;
    int n = blockIdx.x * 8 + warp;
    if (n >= NN) return;

    // --- conv0 scalar SpMM (CSR row sum, lane-per-edge) ---
    int start = g_rowstart[n], len = g_cntI[n];
    float sa = 0.0f, sc = 0.0f;
    for (int base = 0; base < len; base += 32) {
        if (base + lane < len) {
            int s = __ldg(&g_eidx[start + base + lane]);
            float2 ac = __ldg(&g_ac[s]);
            sa += ac.x; sc += ac.y;
        }
    }
    #pragma unroll
    for (int o = 16; o > 0; o >>= 1) {
        sa += __shfl_xor_sync(0xffffffffu, sa, o);
        sc += __shfl_xor_sync(0xffffffffu, sc, o);
    }
    float2 self = __ldg(&g_ac[n]);
    float Sa = self.x + sa;
    float Sc = self.y + sc;

    // --- rank-2 expand + epilogue (dims 2*lane, 2*lane+1) ---
    float2 u2 = ((const float2*)g_uvw)[lane];
    float2 v2 = ((const float2*)(g_uvw + 64))[lane];
    float2 bv = ((const float2*)bcur)[lane];
    float innv = g_inn[n], outv = g_outn[n];

    float hx = leaky((Sa * u2.x + Sc * v2.x) * innv + bv.x) * outv;
    float hy = leaky((Sa * u2.y + Sc * v2.y) * innv + bv.y) * outv;
    Hs[warp][2 * lane]     = hx;
    Hs[warp][2 * lane + 1] = hy;
    __syncwarp();

    // --- conv1 projection: lane computes out dims (2*lane, 2*lane+1) ---
    float acc0 = 0.0f, acc1 = 0.0f;
    const float4* h4 = (const float4*)Hs[warp];
    const float2* W2 = (const float2*)Ws;            // W2[d*32+m] = (W[d][2m], W[d][2m+1])
    #pragma unroll
    for (int d4 = 0; d4 < 16; d4++) {
        float4 hv = h4[d4];
        int b = d4 * 128;                            // 4 rows * 32 float2
        float2 w0 = W2[b + lane];        acc0 += hv.x * w0.x; acc1 += hv.x * w0.y;
        float2 w1 = W2[b + 32 + lane];   acc0 += hv.y * w1.x; acc1 += hv.y * w1.y;
        float2 w2 = W2[b + 64 + lane];   acc0 += hv.z * w2.x; acc1 += hv.z * w2.y;
        float2 w3 = W2[b + 96 + lane];   acc0 += hv.w * w3.x; acc1 += hv.w * w3.y;
    }
    g_ph[n * 32 + lane] = __floats2half2_rn(acc0, acc1);
}

// ---------------- middle SpMM, CSR row-wise (warp-per-row, lane owns 2 dims) ------
// fp16 gathers, fp32 accumulation; fused conv-2 epilogue + scalar projection.
__global__ __launch_bounds__(256) void k_edges_csr(const float* __restrict__ bcur) {
    int gw = (blockIdx.x * blockDim.x + threadIdx.x) >> 5;
    int lane = threadIdx.x & 31;
    if (gw >= NN) return;
    int n = gw;

    float2 acc = __half22float2(__ldg(&g_ph[n * 32 + lane]));   // self-loop
    int start = g_rowstart[n], len = g_cntI[n];
    const int* ep = g_eidx + start;

    int base = 0;
    for (; base + 32 <= len; base += 32) {
        int s_l = __ldg(ep + base + lane);
        #pragma unroll 8
        for (int k = 0; k < 32; k++) {
            int s = __shfl_sync(0xffffffffu, s_l, k);
            float2 v = __half22float2(__ldg(&g_ph[s * 32 + lane]));
            acc.x += v.x; acc.y += v.y;
        }
    }
    int rem = len - base;
    if (rem > 0) {
        int s_l = (lane < rem) ? __ldg(ep + base + lane) : 0;
        for (int k = 0; k < rem; k++) {
            int s = __shfl_sync(0xffffffffu, s_l, k);
            float2 v = __half22float2(__ldg(&g_ph[s * 32 + lane]));
            acc.x += v.x; acc.y += v.y;
        }
    }

    // epilogue: h2 = leaky(acc*inn + bc1)*outn; q = h2 . w2
    float innv = g_inn[n], outv = g_outn[n];
    float2 bv = ((const float2*)bcur)[lane];
    float2 wv = ((const float2*)(g_uvw + 128))[lane];
    float h0 = leaky(acc.x * innv + bv.x) * outv;
    float h1 = leaky(acc.y * innv + bv.y) * outv;
    float s = h0 * wv.x + h1 * wv.y;
    #pragma unroll
    for (int o = 16; o > 0; o >>= 1) s += __shfl_xor_sync(0xffffffffu, s, o);
    if (lane == 0) g_q[n] = s;
}

// ---------------- conv-2 scalar SpMM (CSR) + final output -------------------------
__global__ __launch_bounds__(256) void k_q_csr(float* __restrict__ out) {
    int gw = (blockIdx.x * blockDim.x + threadIdx.x) >> 5;
    int lane = threadIdx.x & 31;
    if (gw >= NN) return;
    int start = g_rowstart[gw], len = g_cntI[gw];
    float acc = 0.0f;
    for (int base = 0; base < len; base += 32) {
        if (base + lane < len) {
            int s = __ldg(&g_eidx[start + base + lane]);
            acc += __ldg(&g_q[s]);
        }
    }
    #pragma unroll
    for (int o = 16; o > 0; o >>= 1) acc += __shfl_xor_sync(0xffffffffu, acc, o);
    if (lane == 0) out[gw] = g_inn[gw] * (__ldg(&g_q[gw]) + acc) + g_c0[0];
}

extern "C" void kernel_launch(void* const* d_in, const int* in_sizes, int n_in,
                              void* d_out, int out_size) {
    const float* weight = (const float*)d_in[0];
    const int*   src    = (const int*)d_in[1];
    const int*   dst    = (const int*)d_in[2];
    const float* W_in   = (const float*)d_in[3];
    const float* b_in   = (const float*)d_in[4];
    const float* Wc     = (const float*)d_in[5];   // [3,64,64]
    const float* bc     = (const float*)d_in[6];   // [3,64]
    const float* W_pred = (const float*)d_in[7];   // [64,1]
    const float* b_pred = (const float*)d_in[8];
    float* out = (float*)d_out;

    (void)in_sizes; (void)n_in; (void)out_size;

    const int EB = (EE + 255) / 256;
    const int NB = (NN + 255) / 256;
    const int WB = (NN * 32 + 255) / 256;          // warp-per-row grids

    k_init<<<NB, 256>>>();
    k_deg<<<EB, 256>>>(src, dst);
    k_scan1<<<NBLK_SCAN, SCAN_B>>>(weight);        // scan + fused norms
    k_scan2<<<1, 256>>>();
    k_scan3<<<NBLK_SCAN, SCAN_B>>>();              // + cursor init
    k_scatter<<<EB, 256>>>(src, dst);
    k_uv<<<17, 256>>>(W_in, b_in, Wc, bc, W_pred, b_pred);

    k_dense1<<<(NN + 7) / 8, 256>>>(Wc + 4096, bc);  // conv0 SpMM + epilogue + conv1 proj
    k_edges_csr<<<WB, 256>>>(bc + 64);               // conv1 SpMM (fp16) + conv2 epi/proj
    k_q_csr<<<WB, 256>>>(out);                       // conv2 scalar SpMM + predictor
}